// round 1
// baseline (speedup 1.0000x reference)
#include <cuda_runtime.h>
#include <math.h>

#define B 4
#define S 2048
#define D 512
#define H 8
#define A 64
#define HA (H*A)

// Scratch (allocation-free rule: __device__ globals)
__device__ float g_q[(size_t)B*H*S*A];     // [b][h][s][a]
__device__ float g_k[(size_t)B*H*S*A];
__device__ float g_v[(size_t)B*H*S*A];
__device__ float g_attn[(size_t)B*S*HA];   // [b][s][h*A+a]  (head-concat layout)

// ---------------------------------------------------------------------------
// Kernel 1: fused QKV projection.
// For each (proj, b, h): out[s, a] = sum_d x[b,s,d] * W[h,d,a] + bias[h,a]
// Tiled GEMM: BM=64, BN=64(=A), BK=16, 16x16 threads, 4x4 microtile per thread.
// grid: (1, S/64, 3*B*H)
// ---------------------------------------------------------------------------
__global__ void proj_kernel(const float* __restrict__ q_in,
                            const float* __restrict__ k_in,
                            const float* __restrict__ v_in,
                            const float* __restrict__ Wq, const float* __restrict__ Wk,
                            const float* __restrict__ Wv,
                            const float* __restrict__ bq, const float* __restrict__ bk,
                            const float* __restrict__ bv)
{
    const int z  = blockIdx.z;            // [0, 3*B*H)
    const int p  = z / (B*H);
    const int bh = z % (B*H);
    const int b  = bh / H;
    const int h  = bh % H;

    const float* x    = (p == 0 ? q_in : p == 1 ? k_in : v_in) + (size_t)b * S * D;
    const float* W    = (p == 0 ? Wq   : p == 1 ? Wk   : Wv)   + (size_t)h * D * A;
    const float* bias = (p == 0 ? bq   : p == 1 ? bk   : bv)   + h * A;
    float* out        = (p == 0 ? g_q  : p == 1 ? g_k  : g_v)  + (size_t)bh * S * A;

    const int s0 = blockIdx.y * 64;
    const int tx = threadIdx.x;           // 0..15
    const int ty = threadIdx.y;           // 0..15
    const int tid = ty * 16 + tx;

    __shared__ float Xs[64][16];          // [row][kk]
    __shared__ float Ws[16][64];          // [kk][col]

    float acc[4][4];
    #pragma unroll
    for (int i = 0; i < 4; i++)
        #pragma unroll
        for (int j = 0; j < 4; j++) acc[i][j] = 0.0f;

    for (int k0 = 0; k0 < D; k0 += 16) {
        // load X tile 64x16 (one float4 per thread)
        {
            int r  = tid / 4;
            int kk = (tid % 4) * 4;
            *(float4*)&Xs[r][kk] = *(const float4*)&x[(size_t)(s0 + r) * D + k0 + kk];
        }
        // load W tile 16x64 (one float4 per thread)
        {
            int kk = tid / 16;
            int c  = (tid % 16) * 4;
            *(float4*)&Ws[kk][c] = *(const float4*)&W[(size_t)(k0 + kk) * A + c];
        }
        __syncthreads();

        #pragma unroll
        for (int kk = 0; kk < 16; kk++) {
            float xr[4], wr[4];
            #pragma unroll
            for (int i = 0; i < 4; i++) xr[i] = Xs[ty * 4 + i][kk];
            float4 w4 = *(const float4*)&Ws[kk][tx * 4];
            wr[0] = w4.x; wr[1] = w4.y; wr[2] = w4.z; wr[3] = w4.w;
            #pragma unroll
            for (int i = 0; i < 4; i++)
                #pragma unroll
                for (int j = 0; j < 4; j++)
                    acc[i][j] += xr[i] * wr[j];
        }
        __syncthreads();
    }

    #pragma unroll
    for (int i = 0; i < 4; i++) {
        int r = ty * 4 + i;
        #pragma unroll
        for (int j = 0; j < 4; j++) {
            int c = tx * 4 + j;
            out[(size_t)(s0 + r) * A + c] = acc[i][j] + bias[c];
        }
    }
}

// ---------------------------------------------------------------------------
// Kernel 2: attention with reference-faithful masking.
// scores = (q . k) / 8 ; masked (j <= i) -> -1e9 ; online softmax over ALL S
// keys (reproduces the uniform softmax on the fully-masked last row exactly).
// One thread per query row. q, accumulator, and block scores in registers;
// K/V blocks (32 x 64) staged in smem (broadcast reads only).
// grid: (S/128, B*H), 128 threads.
// ---------------------------------------------------------------------------
__global__ void __launch_bounds__(128) attn_kernel()
{
    const int bh = blockIdx.y;
    const int b  = bh / H;
    const int h  = bh % H;
    const int i  = blockIdx.x * 128 + threadIdx.x;   // query row
    const int t  = threadIdx.x;

    const float* qp    = g_q + ((size_t)bh * S + i) * A;
    const float* kbase = g_k + (size_t)bh * S * A;
    const float* vbase = g_v + (size_t)bh * S * A;

    float qreg[64], acc[64];
    #pragma unroll
    for (int d = 0; d < 64; d++) {
        qreg[d] = qp[d] * 0.125f;   // 1/sqrt(A)
        acc[d]  = 0.0f;
    }
    float m = -INFINITY, l = 0.0f;

    __shared__ float ks[32][64];
    __shared__ float vs[32][64];

    for (int j0 = 0; j0 < S; j0 += 32) {
        __syncthreads();
        // 2048 floats each of K and V; 128 threads x 4 float4 each
        #pragma unroll
        for (int u = 0; u < 4; u++) {
            int idx = (u * 128 + t) * 4;     // [0, 2048) step 4
            int jj  = idx >> 6;
            int dd  = idx & 63;
            *(float4*)&ks[jj][dd] = *(const float4*)&kbase[(size_t)(j0 + jj) * 64 + dd];
            *(float4*)&vs[jj][dd] = *(const float4*)&vbase[(size_t)(j0 + jj) * 64 + dd];
        }
        __syncthreads();

        float sc[32];
        #pragma unroll
        for (int jj = 0; jj < 32; jj++) {
            float s = 0.0f;
            #pragma unroll
            for (int d = 0; d < 64; d++) s += qreg[d] * ks[jj][d];
            sc[jj] = ((j0 + jj) <= i) ? -1.0e9f : s;
        }

        float bm = sc[0];
        #pragma unroll
        for (int jj = 1; jj < 32; jj++) bm = fmaxf(bm, sc[jj]);
        float m_new = fmaxf(m, bm);
        float corr  = __expf(m - m_new);      // first block: exp(-inf) = 0
        l *= corr;
        #pragma unroll
        for (int d = 0; d < 64; d++) acc[d] *= corr;

        #pragma unroll
        for (int jj = 0; jj < 32; jj++) {
            float pw = __expf(sc[jj] - m_new);
            l += pw;
            #pragma unroll
            for (int d = 0; d < 64; d++) acc[d] += pw * vs[jj][d];
        }
        m = m_new;
    }

    const float inv_l = 1.0f / l;
    float* op = g_attn + ((size_t)b * S + i) * HA + h * A;
    #pragma unroll
    for (int d = 0; d < 64; d += 4) {
        float4 o;
        o.x = acc[d + 0] * inv_l;
        o.y = acc[d + 1] * inv_l;
        o.z = acc[d + 2] * inv_l;
        o.w = acc[d + 3] * inv_l;
        *(float4*)&op[d] = o;
    }
}

// ---------------------------------------------------------------------------
// Kernel 3: output projection. out[M=B*S, N=D] = attn[M, HA] @ Wo[HA, D] + bo
// Same tiling as kernel 1. grid: (D/64, B*S/64)
// ---------------------------------------------------------------------------
__global__ void out_proj_kernel(const float* __restrict__ Wo,
                                const float* __restrict__ bo,
                                float* __restrict__ out)
{
    const int s0 = blockIdx.y * 64;
    const int n0 = blockIdx.x * 64;
    const int tx = threadIdx.x;
    const int ty = threadIdx.y;
    const int tid = ty * 16 + tx;

    __shared__ float Xs[64][16];
    __shared__ float Ws[16][64];

    float acc[4][4];
    #pragma unroll
    for (int i = 0; i < 4; i++)
        #pragma unroll
        for (int j = 0; j < 4; j++) acc[i][j] = 0.0f;

    for (int k0 = 0; k0 < HA; k0 += 16) {
        {
            int r  = tid / 4;
            int kk = (tid % 4) * 4;
            *(float4*)&Xs[r][kk] = *(const float4*)&g_attn[(size_t)(s0 + r) * HA + k0 + kk];
        }
        {
            int kk = tid / 16;
            int c  = (tid % 16) * 4;
            *(float4*)&Ws[kk][c] = *(const float4*)&Wo[(size_t)(k0 + kk) * D + n0 + c];
        }
        __syncthreads();

        #pragma unroll
        for (int kk = 0; kk < 16; kk++) {
            float xr[4], wr[4];
            #pragma unroll
            for (int i = 0; i < 4; i++) xr[i] = Xs[ty * 4 + i][kk];
            float4 w4 = *(const float4*)&Ws[kk][tx * 4];
            wr[0] = w4.x; wr[1] = w4.y; wr[2] = w4.z; wr[3] = w4.w;
            #pragma unroll
            for (int i = 0; i < 4; i++)
                #pragma unroll
                for (int j = 0; j < 4; j++)
                    acc[i][j] += xr[i] * wr[j];
        }
        __syncthreads();
    }

    #pragma unroll
    for (int i = 0; i < 4; i++) {
        int r = ty * 4 + i;
        #pragma unroll
        for (int j = 0; j < 4; j++) {
            int c = tx * 4 + j;
            out[(size_t)(s0 + r) * D + n0 + c] = acc[i][j] + bo[n0 + c];
        }
    }
}

// ---------------------------------------------------------------------------
extern "C" void kernel_launch(void* const* d_in, const int* in_sizes, int n_in,
                              void* d_out, int out_size)
{
    const float* query = (const float*)d_in[0];
    const float* key   = (const float*)d_in[1];
    const float* value = (const float*)d_in[2];
    const float* Wq    = (const float*)d_in[3];
    const float* bq    = (const float*)d_in[4];
    const float* Wk    = (const float*)d_in[5];
    const float* bk    = (const float*)d_in[6];
    const float* Wv    = (const float*)d_in[7];
    const float* bv    = (const float*)d_in[8];
    const float* Wo    = (const float*)d_in[9];
    const float* bo    = (const float*)d_in[10];
    float* out = (float*)d_out;

    (void)in_sizes; (void)n_in; (void)out_size;

    dim3 pthreads(16, 16);
    dim3 pgrid(1, S / 64, 3 * B * H);
    proj_kernel<<<pgrid, pthreads>>>(query, key, value, Wq, Wk, Wv, bq, bk, bv);

    attn_kernel<<<dim3(S / 128, B * H), 128>>>();

    out_proj_kernel<<<dim3(D / 64, (B * S) / 64), pthreads>>>(Wo, bo, out);
}

// round 3
// speedup vs baseline: 2.0437x; 2.0437x over previous
#include <cuda_runtime.h>
#include <math.h>

#define B 4
#define S 2048
#define D 512
#define H 8
#define A 64
#define HA (H*A)

// Scratch (allocation-free rule: __device__ globals)
__device__ float g_q[(size_t)B*H*S*A];     // [b][h][s][a]
__device__ float g_k[(size_t)B*H*S*A];
__device__ float g_v[(size_t)B*H*S*A];
__device__ float g_attn[(size_t)B*S*HA];   // [b][s][h*A+a]  (head-concat layout)

// ---------------------------------------------------------------------------
// Kernel 1: fused QKV projection (fp32, unchanged from R0 baseline).
// ---------------------------------------------------------------------------
__global__ void proj_kernel(const float* __restrict__ q_in,
                            const float* __restrict__ k_in,
                            const float* __restrict__ v_in,
                            const float* __restrict__ Wq, const float* __restrict__ Wk,
                            const float* __restrict__ Wv,
                            const float* __restrict__ bq, const float* __restrict__ bk,
                            const float* __restrict__ bv)
{
    const int z  = blockIdx.z;
    const int p  = z / (B*H);
    const int bh = z % (B*H);
    const int b  = bh / H;
    const int h  = bh % H;

    const float* x    = (p == 0 ? q_in : p == 1 ? k_in : v_in) + (size_t)b * S * D;
    const float* W    = (p == 0 ? Wq   : p == 1 ? Wk   : Wv)   + (size_t)h * D * A;
    const float* bias = (p == 0 ? bq   : p == 1 ? bk   : bv)   + h * A;
    float* out        = (p == 0 ? g_q  : p == 1 ? g_k  : g_v)  + (size_t)bh * S * A;

    const int s0 = blockIdx.y * 64;
    const int tx = threadIdx.x;
    const int ty = threadIdx.y;
    const int tid = ty * 16 + tx;

    __shared__ float Xs[64][16];
    __shared__ float Ws[16][64];

    float acc[4][4];
    #pragma unroll
    for (int i = 0; i < 4; i++)
        #pragma unroll
        for (int j = 0; j < 4; j++) acc[i][j] = 0.0f;

    for (int k0 = 0; k0 < D; k0 += 16) {
        {
            int r  = tid / 4;
            int kk = (tid % 4) * 4;
            *(float4*)&Xs[r][kk] = *(const float4*)&x[(size_t)(s0 + r) * D + k0 + kk];
        }
        {
            int kk = tid / 16;
            int c  = (tid % 16) * 4;
            *(float4*)&Ws[kk][c] = *(const float4*)&W[(size_t)(k0 + kk) * A + c];
        }
        __syncthreads();

        #pragma unroll
        for (int kk = 0; kk < 16; kk++) {
            float xr[4], wr[4];
            #pragma unroll
            for (int i = 0; i < 4; i++) xr[i] = Xs[ty * 4 + i][kk];
            float4 w4 = *(const float4*)&Ws[kk][tx * 4];
            wr[0] = w4.x; wr[1] = w4.y; wr[2] = w4.z; wr[3] = w4.w;
            #pragma unroll
            for (int i = 0; i < 4; i++)
                #pragma unroll
                for (int j = 0; j < 4; j++)
                    acc[i][j] += xr[i] * wr[j];
        }
        __syncthreads();
    }

    #pragma unroll
    for (int i = 0; i < 4; i++) {
        int r = ty * 4 + i;
        #pragma unroll
        for (int j = 0; j < 4; j++) {
            int c = tx * 4 + j;
            out[(size_t)(s0 + r) * A + c] = acc[i][j] + bias[c];
        }
    }
}

// ---------------------------------------------------------------------------
// tf32 mma helpers
// ---------------------------------------------------------------------------
__device__ __forceinline__ unsigned f2tf(float x) {
    unsigned u;
    asm("cvt.rna.tf32.f32 %0, %1;" : "=r"(u) : "f"(x));
    return u;
}

__device__ __forceinline__ void mma_tf32(float c[4], const unsigned a[4],
                                         unsigned b0, unsigned b1) {
    asm volatile("mma.sync.aligned.m16n8k8.row.col.f32.tf32.tf32.f32 "
                 "{%0,%1,%2,%3}, {%4,%5,%6,%7}, {%8,%9}, {%0,%1,%2,%3};"
                 : "+f"(c[0]), "+f"(c[1]), "+f"(c[2]), "+f"(c[3])
                 : "r"(a[0]), "r"(a[1]), "r"(a[2]), "r"(a[3]),
                   "r"(b0), "r"(b1));
}

// XOR swizzle: flip bits [3:5] of the column by row&7 (8-float granule).
#define SW(r, c) ((r)*64 + ((c) ^ (((r)&7) << 3)))

// ---------------------------------------------------------------------------
// Kernel 2: flash-style attention with tf32 tensor cores.
// One CTA = (bh, 64 query rows). 4 warps; warp w owns rows 16w..16w+15.
// Mask: j <= i -> -1e9 (reference-faithful, incl. fully masked last row).
// FIX vs R2: quad-reduce the softmax denominators l0/l1 before normalizing
// (per-thread partials caused 1/0 -> inf -> 0*inf = NaN on nearly-masked rows).
// grid: (S/64, B*H), 128 threads.
// ---------------------------------------------------------------------------
__global__ void __launch_bounds__(128) attn_mma_kernel()
{
    const int bh = blockIdx.y;
    const int b  = bh / H;
    const int h  = bh % H;
    const int qb = blockIdx.x * 64;
    const int tid  = threadIdx.x;
    const int warp = tid >> 5;
    const int lane = tid & 31;
    const int grp  = lane >> 2;   // 0..7 : row within 8-row group / B-frag n
    const int qr   = lane & 3;    // 0..3 : quad index

    __shared__ float Ks[64*64];
    __shared__ float Vs[64*64];
    __shared__ float Ps[64*64];

    // ---- stage Q (scaled by 1/sqrt(A)) via Ks buffer, extract A-frags ----
    const float* qg = g_q + ((size_t)bh * S + qb) * 64;
    #pragma unroll
    for (int u = 0; u < 8; u++) {
        int idx = (u * 128 + tid) * 4;
        int r = idx >> 6, c = idx & 63;
        float4 v = *(const float4*)&qg[idx];
        float* p = &Ks[SW(r, c)];
        p[0] = v.x * 0.125f; p[1] = v.y * 0.125f;
        p[2] = v.z * 0.125f; p[3] = v.w * 0.125f;
    }
    __syncthreads();

    unsigned qf[8][4];
    {
        int r0 = warp * 16 + grp;
        #pragma unroll
        for (int kt = 0; kt < 8; kt++) {
            qf[kt][0] = f2tf(Ks[SW(r0,     kt*8 + qr)]);
            qf[kt][1] = f2tf(Ks[SW(r0 + 8, kt*8 + qr)]);
            qf[kt][2] = f2tf(Ks[SW(r0,     kt*8 + qr + 4)]);
            qf[kt][3] = f2tf(Ks[SW(r0 + 8, kt*8 + qr + 4)]);
        }
    }

    float oacc[8][4];
    #pragma unroll
    for (int nt = 0; nt < 8; nt++)
        #pragma unroll
        for (int j = 0; j < 4; j++) oacc[nt][j] = 0.0f;

    float m0 = -INFINITY, m1 = -INFINITY, l0 = 0.0f, l1 = 0.0f;
    const int i0 = qb + warp * 16 + grp;
    const int i1 = i0 + 8;

    const float* kg = g_k + (size_t)bh * S * 64;
    const float* vg = g_v + (size_t)bh * S * 64;

    for (int j0 = 0; j0 < S; j0 += 64) {
        __syncthreads();
        // ---- stage K, V block (tf32-rounded) ----
        #pragma unroll
        for (int u = 0; u < 8; u++) {
            int idx = (u * 128 + tid) * 4;
            int r = idx >> 6, c = idx & 63;
            float4 kv = *(const float4*)&kg[(size_t)j0 * 64 + idx];
            float4 vv = *(const float4*)&vg[(size_t)j0 * 64 + idx];
            float* pk = &Ks[SW(r, c)];
            pk[0] = __uint_as_float(f2tf(kv.x));
            pk[1] = __uint_as_float(f2tf(kv.y));
            pk[2] = __uint_as_float(f2tf(kv.z));
            pk[3] = __uint_as_float(f2tf(kv.w));
            float* pv = &Vs[SW(r, c)];
            pv[0] = __uint_as_float(f2tf(vv.x));
            pv[1] = __uint_as_float(f2tf(vv.y));
            pv[2] = __uint_as_float(f2tf(vv.z));
            pv[3] = __uint_as_float(f2tf(vv.w));
        }
        __syncthreads();

        // ---- S = Q * K^T ----
        float sacc[8][4];
        #pragma unroll
        for (int nt = 0; nt < 8; nt++)
            #pragma unroll
            for (int j = 0; j < 4; j++) sacc[nt][j] = 0.0f;

        #pragma unroll
        for (int nt = 0; nt < 8; nt++) {
            #pragma unroll
            for (int ks = 0; ks < 8; ks++) {
                unsigned b0 = __float_as_uint(Ks[SW(nt*8 + grp, ks*8 + qr)]);
                unsigned b1 = __float_as_uint(Ks[SW(nt*8 + grp, ks*8 + qr + 4)]);
                mma_tf32(sacc[nt], qf[ks], b0, b1);
            }
        }

        // ---- mask + row max ----
        float tmax0 = -INFINITY, tmax1 = -INFINITY;
        #pragma unroll
        for (int nt = 0; nt < 8; nt++) {
            int j = j0 + nt*8 + 2*qr;
            if (j     <= i0) sacc[nt][0] = -1.0e9f;
            if (j + 1 <= i0) sacc[nt][1] = -1.0e9f;
            if (j     <= i1) sacc[nt][2] = -1.0e9f;
            if (j + 1 <= i1) sacc[nt][3] = -1.0e9f;
            tmax0 = fmaxf(tmax0, fmaxf(sacc[nt][0], sacc[nt][1]));
            tmax1 = fmaxf(tmax1, fmaxf(sacc[nt][2], sacc[nt][3]));
        }
        tmax0 = fmaxf(tmax0, __shfl_xor_sync(0xffffffffu, tmax0, 1));
        tmax0 = fmaxf(tmax0, __shfl_xor_sync(0xffffffffu, tmax0, 2));
        tmax1 = fmaxf(tmax1, __shfl_xor_sync(0xffffffffu, tmax1, 1));
        tmax1 = fmaxf(tmax1, __shfl_xor_sync(0xffffffffu, tmax1, 2));

        float mn0 = fmaxf(m0, tmax0);
        float mn1 = fmaxf(m1, tmax1);
        float cr0 = __expf(m0 - mn0);   // first block: exp(-inf) = 0
        float cr1 = __expf(m1 - mn1);
        l0 *= cr0; l1 *= cr1;
        m0 = mn0;  m1 = mn1;
        #pragma unroll
        for (int nt = 0; nt < 8; nt++) {
            oacc[nt][0] *= cr0; oacc[nt][1] *= cr0;
            oacc[nt][2] *= cr1; oacc[nt][3] *= cr1;
        }

        // ---- p = exp(s - m), accumulate l, store P (tf32) to smem ----
        float ls0 = 0.0f, ls1 = 0.0f;
        {
            int r0 = warp * 16 + grp;
            #pragma unroll
            for (int nt = 0; nt < 8; nt++) {
                float p0 = __expf(sacc[nt][0] - mn0);
                float p1 = __expf(sacc[nt][1] - mn0);
                float p2 = __expf(sacc[nt][2] - mn1);
                float p3 = __expf(sacc[nt][3] - mn1);
                ls0 += p0 + p1; ls1 += p2 + p3;
                int c = nt*8 + 2*qr;
                *(float2*)&Ps[SW(r0, c)] =
                    make_float2(__uint_as_float(f2tf(p0)), __uint_as_float(f2tf(p1)));
                *(float2*)&Ps[SW(r0 + 8, c)] =
                    make_float2(__uint_as_float(f2tf(p2)), __uint_as_float(f2tf(p3)));
            }
        }
        l0 += ls0; l1 += ls1;
        __syncwarp();   // P rows are warp-private; order stores before loads

        // ---- O += P * V ----
        {
            int r0 = warp * 16 + grp;
            #pragma unroll
            for (int ks = 0; ks < 8; ks++) {
                unsigned a[4];
                a[0] = __float_as_uint(Ps[SW(r0,     ks*8 + qr)]);
                a[1] = __float_as_uint(Ps[SW(r0 + 8, ks*8 + qr)]);
                a[2] = __float_as_uint(Ps[SW(r0,     ks*8 + qr + 4)]);
                a[3] = __float_as_uint(Ps[SW(r0 + 8, ks*8 + qr + 4)]);
                #pragma unroll
                for (int nt = 0; nt < 8; nt++) {
                    unsigned b0 = __float_as_uint(Vs[SW(ks*8 + qr,     nt*8 + grp)]);
                    unsigned b1 = __float_as_uint(Vs[SW(ks*8 + qr + 4, nt*8 + grp)]);
                    mma_tf32(oacc[nt], a, b0, b1);
                }
            }
        }
    }

    // ---- FIX: reduce softmax denominators across the quad (each thread only
    // summed its own columns; m is quad-uniform so partials combine exactly) ----
    l0 += __shfl_xor_sync(0xffffffffu, l0, 1);
    l0 += __shfl_xor_sync(0xffffffffu, l0, 2);
    l1 += __shfl_xor_sync(0xffffffffu, l1, 1);
    l1 += __shfl_xor_sync(0xffffffffu, l1, 2);

    // ---- epilogue: normalize, write head-concat layout ----
    const float inv0 = 1.0f / l0;
    const float inv1 = 1.0f / l1;
    float* ob0 = g_attn + ((size_t)b * S + i0) * HA + h * A;
    float* ob1 = g_attn + ((size_t)b * S + i1) * HA + h * A;
    #pragma unroll
    for (int nt = 0; nt < 8; nt++) {
        int c = nt*8 + 2*qr;
        *(float2*)&ob0[c] = make_float2(oacc[nt][0] * inv0, oacc[nt][1] * inv0);
        *(float2*)&ob1[c] = make_float2(oacc[nt][2] * inv1, oacc[nt][3] * inv1);
    }
}

// ---------------------------------------------------------------------------
// Kernel 3: output projection (fp32, unchanged from R0 baseline).
// ---------------------------------------------------------------------------
__global__ void out_proj_kernel(const float* __restrict__ Wo,
                                const float* __restrict__ bo,
                                float* __restrict__ out)
{
    const int s0 = blockIdx.y * 64;
    const int n0 = blockIdx.x * 64;
    const int tx = threadIdx.x;
    const int ty = threadIdx.y;
    const int tid = ty * 16 + tx;

    __shared__ float Xs[64][16];
    __shared__ float Ws[16][64];

    float acc[4][4];
    #pragma unroll
    for (int i = 0; i < 4; i++)
        #pragma unroll
        for (int j = 0; j < 4; j++) acc[i][j] = 0.0f;

    for (int k0 = 0; k0 < HA; k0 += 16) {
        {
            int r  = tid / 4;
            int kk = (tid % 4) * 4;
            *(float4*)&Xs[r][kk] = *(const float4*)&g_attn[(size_t)(s0 + r) * HA + k0 + kk];
        }
        {
            int kk = tid / 16;
            int c  = (tid % 16) * 4;
            *(float4*)&Ws[kk][c] = *(const float4*)&Wo[(size_t)(k0 + kk) * D + n0 + c];
        }
        __syncthreads();

        #pragma unroll
        for (int kk = 0; kk < 16; kk++) {
            float xr[4], wr[4];
            #pragma unroll
            for (int i = 0; i < 4; i++) xr[i] = Xs[ty * 4 + i][kk];
            float4 w4 = *(const float4*)&Ws[kk][tx * 4];
            wr[0] = w4.x; wr[1] = w4.y; wr[2] = w4.z; wr[3] = w4.w;
            #pragma unroll
            for (int i = 0; i < 4; i++)
                #pragma unroll
                for (int j = 0; j < 4; j++)
                    acc[i][j] += xr[i] * wr[j];
        }
        __syncthreads();
    }

    #pragma unroll
    for (int i = 0; i < 4; i++) {
        int r = ty * 4 + i;
        #pragma unroll
        for (int j = 0; j < 4; j++) {
            int c = tx * 4 + j;
            out[(size_t)(s0 + r) * D + n0 + c] = acc[i][j] + bo[n0 + c];
        }
    }
}

// ---------------------------------------------------------------------------
extern "C" void kernel_launch(void* const* d_in, const int* in_sizes, int n_in,
                              void* d_out, int out_size)
{
    const float* query = (const float*)d_in[0];
    const float* key   = (const float*)d_in[1];
    const float* value = (const float*)d_in[2];
    const float* Wq    = (const float*)d_in[3];
    const float* bq    = (const float*)d_in[4];
    const float* Wk    = (const float*)d_in[5];
    const float* bk    = (const float*)d_in[6];
    const float* Wv    = (const float*)d_in[7];
    const float* bv    = (const float*)d_in[8];
    const float* Wo    = (const float*)d_in[9];
    const float* bo    = (const float*)d_in[10];
    float* out = (float*)d_out;

    (void)in_sizes; (void)n_in; (void)out_size;

    dim3 pthreads(16, 16);
    dim3 pgrid(1, S / 64, 3 * B * H);
    proj_kernel<<<pgrid, pthreads>>>(query, key, value, Wq, Wk, Wv, bq, bk, bv);

    attn_mma_kernel<<<dim3(S / 64, B * H), 128>>>();

    out_proj_kernel<<<dim3(D / 64, (B * S) / 64), pthreads>>>(Wo, bo, out);
}

// round 4
// speedup vs baseline: 3.7286x; 1.8244x over previous
#include <cuda_runtime.h>
#include <math.h>

#define B 4
#define S 2048
#define D 512
#define H 8
#define A 64
#define HA (H*A)

// Scratch (allocation-free rule: __device__ globals)
__device__ float g_q[(size_t)B*H*S*A];     // [b][h][s][a]
__device__ float g_k[(size_t)B*H*S*A];
__device__ float g_v[(size_t)B*H*S*A];
__device__ float g_attn[(size_t)B*S*HA];   // [b][s][h*A+a]  (head-concat layout)

// ---------------------------------------------------------------------------
// tf32 mma helpers
// ---------------------------------------------------------------------------
__device__ __forceinline__ unsigned f2tf(float x) {
    unsigned u;
    asm("cvt.rna.tf32.f32 %0, %1;" : "=r"(u) : "f"(x));
    return u;
}

__device__ __forceinline__ void mma_tf32(float c[4], const unsigned a[4],
                                         unsigned b0, unsigned b1) {
    asm volatile("mma.sync.aligned.m16n8k8.row.col.f32.tf32.tf32.f32 "
                 "{%0,%1,%2,%3}, {%4,%5,%6,%7}, {%8,%9}, {%0,%1,%2,%3};"
                 : "+f"(c[0]), "+f"(c[1]), "+f"(c[2]), "+f"(c[3])
                 : "r"(a[0]), "r"(a[1]), "r"(a[2]), "r"(a[3]),
                   "r"(b0), "r"(b1));
}

// XOR swizzle: flip bits [3:5] of the column by row&7 (8-float granule).
#define SW(r, c) ((r)*64 + ((c) ^ (((r)&7) << 3)))

// ---------------------------------------------------------------------------
// Kernel 1: fused QKV projection, tf32 tensor cores.
// CTA = 64(M) x 64(N=A) tile, K-chunks of 64 through swizzled smem.
// 4 warps; warp w owns rows 16w..16w+15 (two m16 row groups).
// grid: (S/64, 3*B*H), 128 threads.
// ---------------------------------------------------------------------------
__global__ void __launch_bounds__(128) proj_tf32_kernel(
    const float* __restrict__ q_in, const float* __restrict__ k_in,
    const float* __restrict__ v_in,
    const float* __restrict__ Wq, const float* __restrict__ Wk,
    const float* __restrict__ Wv,
    const float* __restrict__ bq, const float* __restrict__ bk,
    const float* __restrict__ bv)
{
    const int z  = blockIdx.y;
    const int p  = z / (B*H);
    const int bh = z % (B*H);
    const int b  = bh / H;
    const int h  = bh % H;

    const float* x    = (p == 0 ? q_in : p == 1 ? k_in : v_in) + (size_t)b * S * D;
    const float* W    = (p == 0 ? Wq   : p == 1 ? Wk   : Wv)   + (size_t)h * D * A;
    const float* bias = (p == 0 ? bq   : p == 1 ? bk   : bv)   + h * A;
    float* out        = (p == 0 ? g_q  : p == 1 ? g_k  : g_v)  + (size_t)bh * S * A;

    const int s0   = blockIdx.x * 64;
    const int tid  = threadIdx.x;
    const int warp = tid >> 5;
    const int lane = tid & 31;
    const int grp  = lane >> 2;
    const int qr   = lane & 3;
    const int r0   = warp * 16 + grp;

    __shared__ float Xs[64*64];
    __shared__ float Ws[64*64];   // [k][a]

    float acc[8][4];
    #pragma unroll
    for (int nt = 0; nt < 8; nt++)
        #pragma unroll
        for (int j = 0; j < 4; j++) acc[nt][j] = 0.0f;

    for (int k0 = 0; k0 < D; k0 += 64) {
        __syncthreads();
        #pragma unroll
        for (int u = 0; u < 8; u++) {
            int idx = (u * 128 + tid) * 4;
            int r = idx >> 6, c = idx & 63;
            float4 xv = *(const float4*)&x[(size_t)(s0 + r) * D + k0 + c];
            float* px = &Xs[SW(r, c)];
            px[0] = __uint_as_float(f2tf(xv.x));
            px[1] = __uint_as_float(f2tf(xv.y));
            px[2] = __uint_as_float(f2tf(xv.z));
            px[3] = __uint_as_float(f2tf(xv.w));
            float4 wv = *(const float4*)&W[(size_t)(k0 + r) * A + c];
            float* pw = &Ws[SW(r, c)];
            pw[0] = __uint_as_float(f2tf(wv.x));
            pw[1] = __uint_as_float(f2tf(wv.y));
            pw[2] = __uint_as_float(f2tf(wv.z));
            pw[3] = __uint_as_float(f2tf(wv.w));
        }
        __syncthreads();

        #pragma unroll
        for (int ks = 0; ks < 8; ks++) {
            unsigned af[4];
            af[0] = __float_as_uint(Xs[SW(r0,     ks*8 + qr)]);
            af[1] = __float_as_uint(Xs[SW(r0 + 8, ks*8 + qr)]);
            af[2] = __float_as_uint(Xs[SW(r0,     ks*8 + qr + 4)]);
            af[3] = __float_as_uint(Xs[SW(r0 + 8, ks*8 + qr + 4)]);
            #pragma unroll
            for (int nt = 0; nt < 8; nt++) {
                unsigned b0 = __float_as_uint(Ws[SW(ks*8 + qr,     nt*8 + grp)]);
                unsigned b1 = __float_as_uint(Ws[SW(ks*8 + qr + 4, nt*8 + grp)]);
                mma_tf32(acc[nt], af, b0, b1);
            }
        }
    }

    #pragma unroll
    for (int nt = 0; nt < 8; nt++) {
        int c = nt*8 + 2*qr;
        float2 bv2 = make_float2(bias[c], bias[c+1]);
        *(float2*)&out[(size_t)(s0 + r0) * A + c] =
            make_float2(acc[nt][0] + bv2.x, acc[nt][1] + bv2.y);
        *(float2*)&out[(size_t)(s0 + r0 + 8) * A + c] =
            make_float2(acc[nt][2] + bv2.x, acc[nt][3] + bv2.y);
    }
}

// ---------------------------------------------------------------------------
// Kernel 2: flash-style attention with tf32 tensor cores + causal block-skip.
// Mask kills j <= i, so key blocks with j0 < qb are exactly zero after the
// online-softmax rescale -> skip them. Exception: row S-1 is fully masked
// (reference: uniform softmax over ALL S keys), so the last CTA keeps the
// full loop. grid: (S/64, B*H), 128 threads.
// ---------------------------------------------------------------------------
__global__ void __launch_bounds__(128) attn_mma_kernel()
{
    const int bh = blockIdx.y;
    const int b  = bh / H;
    const int h  = bh % H;
    const int qb = blockIdx.x * 64;
    const int tid  = threadIdx.x;
    const int warp = tid >> 5;
    const int lane = tid & 31;
    const int grp  = lane >> 2;
    const int qr   = lane & 3;

    __shared__ float Ks[64*64];
    __shared__ float Vs[64*64];
    __shared__ float Ps[64*64];

    // ---- stage Q (scaled by 1/sqrt(A)) via Ks buffer, extract A-frags ----
    const float* qg = g_q + ((size_t)bh * S + qb) * 64;
    #pragma unroll
    for (int u = 0; u < 8; u++) {
        int idx = (u * 128 + tid) * 4;
        int r = idx >> 6, c = idx & 63;
        float4 v = *(const float4*)&qg[idx];
        float* p = &Ks[SW(r, c)];
        p[0] = v.x * 0.125f; p[1] = v.y * 0.125f;
        p[2] = v.z * 0.125f; p[3] = v.w * 0.125f;
    }
    __syncthreads();

    unsigned qf[8][4];
    {
        int r0 = warp * 16 + grp;
        #pragma unroll
        for (int kt = 0; kt < 8; kt++) {
            qf[kt][0] = f2tf(Ks[SW(r0,     kt*8 + qr)]);
            qf[kt][1] = f2tf(Ks[SW(r0 + 8, kt*8 + qr)]);
            qf[kt][2] = f2tf(Ks[SW(r0,     kt*8 + qr + 4)]);
            qf[kt][3] = f2tf(Ks[SW(r0 + 8, kt*8 + qr + 4)]);
        }
    }

    float oacc[8][4];
    #pragma unroll
    for (int nt = 0; nt < 8; nt++)
        #pragma unroll
        for (int j = 0; j < 4; j++) oacc[nt][j] = 0.0f;

    float m0 = -INFINITY, m1 = -INFINITY, l0 = 0.0f, l1 = 0.0f;
    const int i0 = qb + warp * 16 + grp;
    const int i1 = i0 + 8;

    const float* kg = g_k + (size_t)bh * S * 64;
    const float* vg = g_v + (size_t)bh * S * 64;

    // Causal skip: blocks with j0+63 <= qb-1 are fully masked for every row
    // in this CTA and contribute exactly 0. Last CTA holds row S-1 (fully
    // masked everywhere -> uniform over all S keys) so it keeps j_start=0.
    const int j_start = (qb == S - 64) ? 0 : qb;

    for (int j0 = j_start; j0 < S; j0 += 64) {
        __syncthreads();
        // ---- stage K, V block (tf32-rounded) ----
        #pragma unroll
        for (int u = 0; u < 8; u++) {
            int idx = (u * 128 + tid) * 4;
            int r = idx >> 6, c = idx & 63;
            float4 kv = *(const float4*)&kg[(size_t)j0 * 64 + idx];
            float4 vv = *(const float4*)&vg[(size_t)j0 * 64 + idx];
            float* pk = &Ks[SW(r, c)];
            pk[0] = __uint_as_float(f2tf(kv.x));
            pk[1] = __uint_as_float(f2tf(kv.y));
            pk[2] = __uint_as_float(f2tf(kv.z));
            pk[3] = __uint_as_float(f2tf(kv.w));
            float* pv = &Vs[SW(r, c)];
            pv[0] = __uint_as_float(f2tf(vv.x));
            pv[1] = __uint_as_float(f2tf(vv.y));
            pv[2] = __uint_as_float(f2tf(vv.z));
            pv[3] = __uint_as_float(f2tf(vv.w));
        }
        __syncthreads();

        // ---- S = Q * K^T ----
        float sacc[8][4];
        #pragma unroll
        for (int nt = 0; nt < 8; nt++)
            #pragma unroll
            for (int j = 0; j < 4; j++) sacc[nt][j] = 0.0f;

        #pragma unroll
        for (int nt = 0; nt < 8; nt++) {
            #pragma unroll
            for (int ks = 0; ks < 8; ks++) {
                unsigned b0 = __float_as_uint(Ks[SW(nt*8 + grp, ks*8 + qr)]);
                unsigned b1 = __float_as_uint(Ks[SW(nt*8 + grp, ks*8 + qr + 4)]);
                mma_tf32(sacc[nt], qf[ks], b0, b1);
            }
        }

        // ---- mask + row max ----
        float tmax0 = -INFINITY, tmax1 = -INFINITY;
        #pragma unroll
        for (int nt = 0; nt < 8; nt++) {
            int j = j0 + nt*8 + 2*qr;
            if (j     <= i0) sacc[nt][0] = -1.0e9f;
            if (j + 1 <= i0) sacc[nt][1] = -1.0e9f;
            if (j     <= i1) sacc[nt][2] = -1.0e9f;
            if (j + 1 <= i1) sacc[nt][3] = -1.0e9f;
            tmax0 = fmaxf(tmax0, fmaxf(sacc[nt][0], sacc[nt][1]));
            tmax1 = fmaxf(tmax1, fmaxf(sacc[nt][2], sacc[nt][3]));
        }
        tmax0 = fmaxf(tmax0, __shfl_xor_sync(0xffffffffu, tmax0, 1));
        tmax0 = fmaxf(tmax0, __shfl_xor_sync(0xffffffffu, tmax0, 2));
        tmax1 = fmaxf(tmax1, __shfl_xor_sync(0xffffffffu, tmax1, 1));
        tmax1 = fmaxf(tmax1, __shfl_xor_sync(0xffffffffu, tmax1, 2));

        float mn0 = fmaxf(m0, tmax0);
        float mn1 = fmaxf(m1, tmax1);
        float cr0 = __expf(m0 - mn0);   // first block: exp(-inf) = 0
        float cr1 = __expf(m1 - mn1);
        l0 *= cr0; l1 *= cr1;
        m0 = mn0;  m1 = mn1;
        #pragma unroll
        for (int nt = 0; nt < 8; nt++) {
            oacc[nt][0] *= cr0; oacc[nt][1] *= cr0;
            oacc[nt][2] *= cr1; oacc[nt][3] *= cr1;
        }

        // ---- p = exp(s - m), accumulate l, store P (tf32) to smem ----
        float ls0 = 0.0f, ls1 = 0.0f;
        {
            int r0 = warp * 16 + grp;
            #pragma unroll
            for (int nt = 0; nt < 8; nt++) {
                float p0 = __expf(sacc[nt][0] - mn0);
                float p1 = __expf(sacc[nt][1] - mn0);
                float p2 = __expf(sacc[nt][2] - mn1);
                float p3 = __expf(sacc[nt][3] - mn1);
                ls0 += p0 + p1; ls1 += p2 + p3;
                int c = nt*8 + 2*qr;
                *(float2*)&Ps[SW(r0, c)] =
                    make_float2(__uint_as_float(f2tf(p0)), __uint_as_float(f2tf(p1)));
                *(float2*)&Ps[SW(r0 + 8, c)] =
                    make_float2(__uint_as_float(f2tf(p2)), __uint_as_float(f2tf(p3)));
            }
        }
        l0 += ls0; l1 += ls1;
        __syncwarp();   // P rows are warp-private; order stores before loads

        // ---- O += P * V ----
        {
            int r0 = warp * 16 + grp;
            #pragma unroll
            for (int ks = 0; ks < 8; ks++) {
                unsigned a[4];
                a[0] = __float_as_uint(Ps[SW(r0,     ks*8 + qr)]);
                a[1] = __float_as_uint(Ps[SW(r0 + 8, ks*8 + qr)]);
                a[2] = __float_as_uint(Ps[SW(r0,     ks*8 + qr + 4)]);
                a[3] = __float_as_uint(Ps[SW(r0 + 8, ks*8 + qr + 4)]);
                #pragma unroll
                for (int nt = 0; nt < 8; nt++) {
                    unsigned b0 = __float_as_uint(Vs[SW(ks*8 + qr,     nt*8 + grp)]);
                    unsigned b1 = __float_as_uint(Vs[SW(ks*8 + qr + 4, nt*8 + grp)]);
                    mma_tf32(oacc[nt], a, b0, b1);
                }
            }
        }
    }

    // ---- reduce softmax denominators across the quad ----
    l0 += __shfl_xor_sync(0xffffffffu, l0, 1);
    l0 += __shfl_xor_sync(0xffffffffu, l0, 2);
    l1 += __shfl_xor_sync(0xffffffffu, l1, 1);
    l1 += __shfl_xor_sync(0xffffffffu, l1, 2);

    // ---- epilogue: normalize, write head-concat layout ----
    const float inv0 = 1.0f / l0;
    const float inv1 = 1.0f / l1;
    float* ob0 = g_attn + ((size_t)b * S + i0) * HA + h * A;
    float* ob1 = g_attn + ((size_t)b * S + i1) * HA + h * A;
    #pragma unroll
    for (int nt = 0; nt < 8; nt++) {
        int c = nt*8 + 2*qr;
        *(float2*)&ob0[c] = make_float2(oacc[nt][0] * inv0, oacc[nt][1] * inv0);
        *(float2*)&ob1[c] = make_float2(oacc[nt][2] * inv1, oacc[nt][3] * inv1);
    }
}

// ---------------------------------------------------------------------------
// Kernel 3: output projection, tf32 tensor cores.
// out[M=B*S, N=D] = g_attn[M, HA] @ Wo[HA, D] + bo
// CTA 64x64 tile, same machinery. grid: (D/64, B*S/64), 128 threads.
// ---------------------------------------------------------------------------
__global__ void __launch_bounds__(128) out_proj_tf32_kernel(
    const float* __restrict__ Wo, const float* __restrict__ bo,
    float* __restrict__ out)
{
    const int n0 = blockIdx.x * 64;
    const int s0 = blockIdx.y * 64;
    const int tid  = threadIdx.x;
    const int warp = tid >> 5;
    const int lane = tid & 31;
    const int grp  = lane >> 2;
    const int qr   = lane & 3;
    const int r0   = warp * 16 + grp;

    __shared__ float Xs[64*64];
    __shared__ float Ws[64*64];   // [k][n]

    float acc[8][4];
    #pragma unroll
    for (int nt = 0; nt < 8; nt++)
        #pragma unroll
        for (int j = 0; j < 4; j++) acc[nt][j] = 0.0f;

    for (int k0 = 0; k0 < HA; k0 += 64) {
        __syncthreads();
        #pragma unroll
        for (int u = 0; u < 8; u++) {
            int idx = (u * 128 + tid) * 4;
            int r = idx >> 6, c = idx & 63;
            float4 xv = *(const float4*)&g_attn[(size_t)(s0 + r) * HA + k0 + c];
            float* px = &Xs[SW(r, c)];
            px[0] = __uint_as_float(f2tf(xv.x));
            px[1] = __uint_as_float(f2tf(xv.y));
            px[2] = __uint_as_float(f2tf(xv.z));
            px[3] = __uint_as_float(f2tf(xv.w));
            float4 wv = *(const float4*)&Wo[(size_t)(k0 + r) * D + n0 + c];
            float* pw = &Ws[SW(r, c)];
            pw[0] = __uint_as_float(f2tf(wv.x));
            pw[1] = __uint_as_float(f2tf(wv.y));
            pw[2] = __uint_as_float(f2tf(wv.z));
            pw[3] = __uint_as_float(f2tf(wv.w));
        }
        __syncthreads();

        #pragma unroll
        for (int ks = 0; ks < 8; ks++) {
            unsigned af[4];
            af[0] = __float_as_uint(Xs[SW(r0,     ks*8 + qr)]);
            af[1] = __float_as_uint(Xs[SW(r0 + 8, ks*8 + qr)]);
            af[2] = __float_as_uint(Xs[SW(r0,     ks*8 + qr + 4)]);
            af[3] = __float_as_uint(Xs[SW(r0 + 8, ks*8 + qr + 4)]);
            #pragma unroll
            for (int nt = 0; nt < 8; nt++) {
                unsigned b0 = __float_as_uint(Ws[SW(ks*8 + qr,     nt*8 + grp)]);
                unsigned b1 = __float_as_uint(Ws[SW(ks*8 + qr + 4, nt*8 + grp)]);
                mma_tf32(acc[nt], af, b0, b1);
            }
        }
    }

    #pragma unroll
    for (int nt = 0; nt < 8; nt++) {
        int c = nt*8 + 2*qr;
        float2 bv2 = make_float2(bo[n0 + c], bo[n0 + c + 1]);
        *(float2*)&out[(size_t)(s0 + r0) * D + n0 + c] =
            make_float2(acc[nt][0] + bv2.x, acc[nt][1] + bv2.y);
        *(float2*)&out[(size_t)(s0 + r0 + 8) * D + n0 + c] =
            make_float2(acc[nt][2] + bv2.x, acc[nt][3] + bv2.y);
    }
}

// ---------------------------------------------------------------------------
extern "C" void kernel_launch(void* const* d_in, const int* in_sizes, int n_in,
                              void* d_out, int out_size)
{
    const float* query = (const float*)d_in[0];
    const float* key   = (const float*)d_in[1];
    const float* value = (const float*)d_in[2];
    const float* Wq    = (const float*)d_in[3];
    const float* bq    = (const float*)d_in[4];
    const float* Wk    = (const float*)d_in[5];
    const float* bk    = (const float*)d_in[6];
    const float* Wv    = (const float*)d_in[7];
    const float* bv    = (const float*)d_in[8];
    const float* Wo    = (const float*)d_in[9];
    const float* bo    = (const float*)d_in[10];
    float* out = (float*)d_out;

    (void)in_sizes; (void)n_in; (void)out_size;

    proj_tf32_kernel<<<dim3(S / 64, 3 * B * H), 128>>>(query, key, value,
                                                       Wq, Wk, Wv, bq, bk, bv);

    attn_mma_kernel<<<dim3(S / 64, B * H), 128>>>();

    out_proj_tf32_kernel<<<dim3(D / 64, (B * S) / 64), 128>>>(Wo, bo, out);
}

// round 5
// speedup vs baseline: 3.9619x; 1.0626x over previous
#include <cuda_runtime.h>
#include <math.h>

#define B 4
#define S 2048
#define D 512
#define H 8
#define A 64
#define HA (H*A)

// Scratch (allocation-free rule: __device__ globals)
__device__ float g_q[(size_t)B*H*S*A];     // [b][h][s][a]
__device__ float g_k[(size_t)B*H*S*A];
__device__ float g_v[(size_t)B*H*S*A];
__device__ float g_attn[(size_t)B*S*HA];   // [b][s][h*A+a]  (head-concat layout)

// ---------------------------------------------------------------------------
// tf32 mma helpers
// ---------------------------------------------------------------------------
__device__ __forceinline__ unsigned f2tf(float x) {
    unsigned u;
    asm("cvt.rna.tf32.f32 %0, %1;" : "=r"(u) : "f"(x));
    return u;
}

__device__ __forceinline__ void mma_tf32(float c[4], const unsigned a[4],
                                         unsigned b0, unsigned b1) {
    asm volatile("mma.sync.aligned.m16n8k8.row.col.f32.tf32.tf32.f32 "
                 "{%0,%1,%2,%3}, {%4,%5,%6,%7}, {%8,%9}, {%0,%1,%2,%3};"
                 : "+f"(c[0]), "+f"(c[1]), "+f"(c[2]), "+f"(c[3])
                 : "r"(a[0]), "r"(a[1]), "r"(a[2]), "r"(a[3]),
                   "r"(b0), "r"(b1));
}

// XOR swizzle: flip bits [3:5] of the column by row&7 (8-float granule).
#define SW(r, c) ((r)*64 + ((c) ^ (((r)&7) << 3)))

// ---------------------------------------------------------------------------
// Kernel 1: fused QKV projection, tf32, 32-row warp tiles.
// CTA = 128(M) x 64(N=A), 4 warps, warp w owns rows 32w..32w+31 (2 m16 groups).
// K-chunks of 64 through swizzled smem. 1.5 LDS/MMA in the hot loop.
// grid: (S/128, 3*B*H), 128 threads.
// ---------------------------------------------------------------------------
__global__ void __launch_bounds__(128) proj_tf32_kernel(
    const float* __restrict__ q_in, const float* __restrict__ k_in,
    const float* __restrict__ v_in,
    const float* __restrict__ Wq, const float* __restrict__ Wk,
    const float* __restrict__ Wv,
    const float* __restrict__ bq, const float* __restrict__ bk,
    const float* __restrict__ bv)
{
    const int z  = blockIdx.y;
    const int p  = z / (B*H);
    const int bh = z % (B*H);
    const int b  = bh / H;
    const int h  = bh % H;

    const float* x    = (p == 0 ? q_in : p == 1 ? k_in : v_in) + (size_t)b * S * D;
    const float* W    = (p == 0 ? Wq   : p == 1 ? Wk   : Wv)   + (size_t)h * D * A;
    const float* bias = (p == 0 ? bq   : p == 1 ? bk   : bv)   + h * A;
    float* out        = (p == 0 ? g_q  : p == 1 ? g_k  : g_v)  + (size_t)bh * S * A;

    const int s0   = blockIdx.x * 128;
    const int tid  = threadIdx.x;
    const int warp = tid >> 5;
    const int lane = tid & 31;
    const int grp  = lane >> 2;
    const int qr   = lane & 3;

    __shared__ float Xs[128*64];
    __shared__ float Ws[64*64];   // [k][a]

    float acc[2][8][4];
    #pragma unroll
    for (int g = 0; g < 2; g++)
        #pragma unroll
        for (int nt = 0; nt < 8; nt++)
            #pragma unroll
            for (int j = 0; j < 4; j++) acc[g][nt][j] = 0.0f;

    for (int k0 = 0; k0 < D; k0 += 64) {
        __syncthreads();
        #pragma unroll
        for (int u = 0; u < 16; u++) {
            int idx = (u * 128 + tid) * 4;
            int r = idx >> 6, c = idx & 63;
            float4 xv = *(const float4*)&x[(size_t)(s0 + r) * D + k0 + c];
            float* px = &Xs[SW(r, c)];
            px[0] = __uint_as_float(f2tf(xv.x));
            px[1] = __uint_as_float(f2tf(xv.y));
            px[2] = __uint_as_float(f2tf(xv.z));
            px[3] = __uint_as_float(f2tf(xv.w));
        }
        #pragma unroll
        for (int u = 0; u < 8; u++) {
            int idx = (u * 128 + tid) * 4;
            int r = idx >> 6, c = idx & 63;
            float4 wv = *(const float4*)&W[(size_t)(k0 + r) * A + c];
            float* pw = &Ws[SW(r, c)];
            pw[0] = __uint_as_float(f2tf(wv.x));
            pw[1] = __uint_as_float(f2tf(wv.y));
            pw[2] = __uint_as_float(f2tf(wv.z));
            pw[3] = __uint_as_float(f2tf(wv.w));
        }
        __syncthreads();

        #pragma unroll
        for (int ks = 0; ks < 8; ks++) {
            unsigned af[2][4];
            #pragma unroll
            for (int g = 0; g < 2; g++) {
                int rb = warp * 32 + g * 16 + grp;
                af[g][0] = __float_as_uint(Xs[SW(rb,     ks*8 + qr)]);
                af[g][1] = __float_as_uint(Xs[SW(rb + 8, ks*8 + qr)]);
                af[g][2] = __float_as_uint(Xs[SW(rb,     ks*8 + qr + 4)]);
                af[g][3] = __float_as_uint(Xs[SW(rb + 8, ks*8 + qr + 4)]);
            }
            #pragma unroll
            for (int nt = 0; nt < 8; nt++) {
                unsigned b0 = __float_as_uint(Ws[SW(ks*8 + qr,     nt*8 + grp)]);
                unsigned b1 = __float_as_uint(Ws[SW(ks*8 + qr + 4, nt*8 + grp)]);
                mma_tf32(acc[0][nt], af[0], b0, b1);
                mma_tf32(acc[1][nt], af[1], b0, b1);
            }
        }
    }

    #pragma unroll
    for (int g = 0; g < 2; g++) {
        int rb = warp * 32 + g * 16 + grp;
        #pragma unroll
        for (int nt = 0; nt < 8; nt++) {
            int c = nt*8 + 2*qr;
            float2 bv2 = make_float2(bias[c], bias[c+1]);
            *(float2*)&out[(size_t)(s0 + rb) * A + c] =
                make_float2(acc[g][nt][0] + bv2.x, acc[g][nt][1] + bv2.y);
            *(float2*)&out[(size_t)(s0 + rb + 8) * A + c] =
                make_float2(acc[g][nt][2] + bv2.x, acc[g][nt][3] + bv2.y);
        }
    }
}

// ---------------------------------------------------------------------------
// Kernel 2: flash attention, tf32, 128 query rows per CTA (32 rows/warp).
// Dynamic smem (96KB): Qs 128x64 | Ks 64x64 | Vs 64x64 | Ps 128x64.
// Causal block-skip (j<=i masked): blocks with j0 < qb fully masked -> skip;
// last CTA (holds row S-1, fully masked -> uniform over ALL S keys) keeps
// the full loop. Underflow-wipe makes processed dead blocks exactly 0.
// grid: (S/128, B*H), 128 threads.
// ---------------------------------------------------------------------------
__global__ void __launch_bounds__(128) attn_mma_kernel()
{
    extern __shared__ float sm[];
    float* Qs = sm;              // 128*64
    float* Ks = sm + 8192;       // 64*64
    float* Vs = sm + 12288;      // 64*64
    float* Ps = sm + 16384;      // 128*64

    const int bh = blockIdx.y;
    const int b  = bh / H;
    const int h  = bh % H;
    const int qb = blockIdx.x * 128;
    const int tid  = threadIdx.x;
    const int warp = tid >> 5;
    const int lane = tid & 31;
    const int grp  = lane >> 2;
    const int qr   = lane & 3;

    // ---- stage Q (scaled by 1/sqrt(A)) ----
    const float* qg = g_q + ((size_t)bh * S + qb) * 64;
    #pragma unroll
    for (int u = 0; u < 16; u++) {
        int idx = (u * 128 + tid) * 4;
        int r = idx >> 6, c = idx & 63;
        float4 v = *(const float4*)&qg[idx];
        float* p = &Qs[SW(r, c)];
        p[0] = __uint_as_float(f2tf(v.x * 0.125f));
        p[1] = __uint_as_float(f2tf(v.y * 0.125f));
        p[2] = __uint_as_float(f2tf(v.z * 0.125f));
        p[3] = __uint_as_float(f2tf(v.w * 0.125f));
    }

    float oacc[2][8][4];
    #pragma unroll
    for (int g = 0; g < 2; g++)
        #pragma unroll
        for (int nt = 0; nt < 8; nt++)
            #pragma unroll
            for (int j = 0; j < 4; j++) oacc[g][nt][j] = 0.0f;

    // softmax state: index 2g+0 -> row iA(g), 2g+1 -> row iB(g)=iA+8
    float m[4], l[4];
    #pragma unroll
    for (int q = 0; q < 4; q++) { m[q] = -INFINITY; l[q] = 0.0f; }

    const float* kg = g_k + (size_t)bh * S * 64;
    const float* vg = g_v + (size_t)bh * S * 64;

    const int j_start = (qb == S - 128) ? 0 : qb;

    for (int j0 = j_start; j0 < S; j0 += 64) {
        __syncthreads();
        // ---- stage K, V block (tf32-rounded) ----
        #pragma unroll
        for (int u = 0; u < 8; u++) {
            int idx = (u * 128 + tid) * 4;
            int r = idx >> 6, c = idx & 63;
            float4 kv = *(const float4*)&kg[(size_t)j0 * 64 + idx];
            float4 vv = *(const float4*)&vg[(size_t)j0 * 64 + idx];
            float* pk = &Ks[SW(r, c)];
            pk[0] = __uint_as_float(f2tf(kv.x));
            pk[1] = __uint_as_float(f2tf(kv.y));
            pk[2] = __uint_as_float(f2tf(kv.z));
            pk[3] = __uint_as_float(f2tf(kv.w));
            float* pv = &Vs[SW(r, c)];
            pv[0] = __uint_as_float(f2tf(vv.x));
            pv[1] = __uint_as_float(f2tf(vv.y));
            pv[2] = __uint_as_float(f2tf(vv.z));
            pv[3] = __uint_as_float(f2tf(vv.w));
        }
        __syncthreads();

        // ---- S = Q * K^T ----
        float sacc[2][8][4];
        #pragma unroll
        for (int g = 0; g < 2; g++)
            #pragma unroll
            for (int nt = 0; nt < 8; nt++)
                #pragma unroll
                for (int j = 0; j < 4; j++) sacc[g][nt][j] = 0.0f;

        #pragma unroll
        for (int ks = 0; ks < 8; ks++) {
            unsigned qa[2][4];
            #pragma unroll
            for (int g = 0; g < 2; g++) {
                int rb = warp * 32 + g * 16 + grp;
                qa[g][0] = __float_as_uint(Qs[SW(rb,     ks*8 + qr)]);
                qa[g][1] = __float_as_uint(Qs[SW(rb + 8, ks*8 + qr)]);
                qa[g][2] = __float_as_uint(Qs[SW(rb,     ks*8 + qr + 4)]);
                qa[g][3] = __float_as_uint(Qs[SW(rb + 8, ks*8 + qr + 4)]);
            }
            #pragma unroll
            for (int nt = 0; nt < 8; nt++) {
                unsigned b0 = __float_as_uint(Ks[SW(nt*8 + grp, ks*8 + qr)]);
                unsigned b1 = __float_as_uint(Ks[SW(nt*8 + grp, ks*8 + qr + 4)]);
                mma_tf32(sacc[0][nt], qa[0], b0, b1);
                mma_tf32(sacc[1][nt], qa[1], b0, b1);
            }
        }

        // ---- mask + online softmax per row group ----
        #pragma unroll
        for (int g = 0; g < 2; g++) {
            const int iA = qb + warp * 32 + g * 16 + grp;
            const int iB = iA + 8;
            float tmaxA = -INFINITY, tmaxB = -INFINITY;
            #pragma unroll
            for (int nt = 0; nt < 8; nt++) {
                int j = j0 + nt*8 + 2*qr;
                if (j     <= iA) sacc[g][nt][0] = -1.0e9f;
                if (j + 1 <= iA) sacc[g][nt][1] = -1.0e9f;
                if (j     <= iB) sacc[g][nt][2] = -1.0e9f;
                if (j + 1 <= iB) sacc[g][nt][3] = -1.0e9f;
                tmaxA = fmaxf(tmaxA, fmaxf(sacc[g][nt][0], sacc[g][nt][1]));
                tmaxB = fmaxf(tmaxB, fmaxf(sacc[g][nt][2], sacc[g][nt][3]));
            }
            tmaxA = fmaxf(tmaxA, __shfl_xor_sync(0xffffffffu, tmaxA, 1));
            tmaxA = fmaxf(tmaxA, __shfl_xor_sync(0xffffffffu, tmaxA, 2));
            tmaxB = fmaxf(tmaxB, __shfl_xor_sync(0xffffffffu, tmaxB, 1));
            tmaxB = fmaxf(tmaxB, __shfl_xor_sync(0xffffffffu, tmaxB, 2));

            float mnA = fmaxf(m[2*g],   tmaxA);
            float mnB = fmaxf(m[2*g+1], tmaxB);
            float crA = __expf(m[2*g]   - mnA);   // first block: exp(-inf)=0
            float crB = __expf(m[2*g+1] - mnB);
            l[2*g]   *= crA; l[2*g+1] *= crB;
            m[2*g]    = mnA; m[2*g+1]  = mnB;
            #pragma unroll
            for (int nt = 0; nt < 8; nt++) {
                oacc[g][nt][0] *= crA; oacc[g][nt][1] *= crA;
                oacc[g][nt][2] *= crB; oacc[g][nt][3] *= crB;
            }

            float lsA = 0.0f, lsB = 0.0f;
            int rb = warp * 32 + g * 16 + grp;
            #pragma unroll
            for (int nt = 0; nt < 8; nt++) {
                float p0 = __expf(sacc[g][nt][0] - mnA);
                float p1 = __expf(sacc[g][nt][1] - mnA);
                float p2 = __expf(sacc[g][nt][2] - mnB);
                float p3 = __expf(sacc[g][nt][3] - mnB);
                lsA += p0 + p1; lsB += p2 + p3;
                int c = nt*8 + 2*qr;
                *(float2*)&Ps[SW(rb, c)] =
                    make_float2(__uint_as_float(f2tf(p0)), __uint_as_float(f2tf(p1)));
                *(float2*)&Ps[SW(rb + 8, c)] =
                    make_float2(__uint_as_float(f2tf(p2)), __uint_as_float(f2tf(p3)));
            }
            l[2*g] += lsA; l[2*g+1] += lsB;
        }
        __syncwarp();   // P rows are warp-private; order stores before loads

        // ---- O += P * V ----
        #pragma unroll
        for (int ks = 0; ks < 8; ks++) {
            unsigned pa[2][4];
            #pragma unroll
            for (int g = 0; g < 2; g++) {
                int rb = warp * 32 + g * 16 + grp;
                pa[g][0] = __float_as_uint(Ps[SW(rb,     ks*8 + qr)]);
                pa[g][1] = __float_as_uint(Ps[SW(rb + 8, ks*8 + qr)]);
                pa[g][2] = __float_as_uint(Ps[SW(rb,     ks*8 + qr + 4)]);
                pa[g][3] = __float_as_uint(Ps[SW(rb + 8, ks*8 + qr + 4)]);
            }
            #pragma unroll
            for (int nt = 0; nt < 8; nt++) {
                unsigned b0 = __float_as_uint(Vs[SW(ks*8 + qr,     nt*8 + grp)]);
                unsigned b1 = __float_as_uint(Vs[SW(ks*8 + qr + 4, nt*8 + grp)]);
                mma_tf32(oacc[0][nt], pa[0], b0, b1);
                mma_tf32(oacc[1][nt], pa[1], b0, b1);
            }
        }
    }

    // ---- quad-reduce softmax denominators (partials per thread) ----
    #pragma unroll
    for (int q = 0; q < 4; q++) {
        l[q] += __shfl_xor_sync(0xffffffffu, l[q], 1);
        l[q] += __shfl_xor_sync(0xffffffffu, l[q], 2);
    }

    // ---- epilogue: normalize, write head-concat layout ----
    #pragma unroll
    for (int g = 0; g < 2; g++) {
        const int iA = qb + warp * 32 + g * 16 + grp;
        const float invA = 1.0f / l[2*g];
        const float invB = 1.0f / l[2*g+1];
        float* obA = g_attn + ((size_t)b * S + iA) * HA + h * A;
        float* obB = g_attn + ((size_t)b * S + iA + 8) * HA + h * A;
        #pragma unroll
        for (int nt = 0; nt < 8; nt++) {
            int c = nt*8 + 2*qr;
            *(float2*)&obA[c] = make_float2(oacc[g][nt][0] * invA, oacc[g][nt][1] * invA);
            *(float2*)&obB[c] = make_float2(oacc[g][nt][2] * invB, oacc[g][nt][3] * invB);
        }
    }
}

// ---------------------------------------------------------------------------
// Kernel 3: output projection, tf32, 32-row warp tiles.
// out[M=B*S, N=D] = g_attn[M, HA] @ Wo[HA, D] + bo
// CTA 128x64. grid: (D/64, B*S/128), 128 threads.
// ---------------------------------------------------------------------------
__global__ void __launch_bounds__(128) out_proj_tf32_kernel(
    const float* __restrict__ Wo, const float* __restrict__ bo,
    float* __restrict__ out)
{
    const int n0 = blockIdx.x * 64;
    const int s0 = blockIdx.y * 128;
    const int tid  = threadIdx.x;
    const int warp = tid >> 5;
    const int lane = tid & 31;
    const int grp  = lane >> 2;
    const int qr   = lane & 3;

    __shared__ float Xs[128*64];
    __shared__ float Ws[64*64];   // [k][n]

    float acc[2][8][4];
    #pragma unroll
    for (int g = 0; g < 2; g++)
        #pragma unroll
        for (int nt = 0; nt < 8; nt++)
            #pragma unroll
            for (int j = 0; j < 4; j++) acc[g][nt][j] = 0.0f;

    for (int k0 = 0; k0 < HA; k0 += 64) {
        __syncthreads();
        #pragma unroll
        for (int u = 0; u < 16; u++) {
            int idx = (u * 128 + tid) * 4;
            int r = idx >> 6, c = idx & 63;
            float4 xv = *(const float4*)&g_attn[(size_t)(s0 + r) * HA + k0 + c];
            float* px = &Xs[SW(r, c)];
            px[0] = __uint_as_float(f2tf(xv.x));
            px[1] = __uint_as_float(f2tf(xv.y));
            px[2] = __uint_as_float(f2tf(xv.z));
            px[3] = __uint_as_float(f2tf(xv.w));
        }
        #pragma unroll
        for (int u = 0; u < 8; u++) {
            int idx = (u * 128 + tid) * 4;
            int r = idx >> 6, c = idx & 63;
            float4 wv = *(const float4*)&Wo[(size_t)(k0 + r) * D + n0 + c];
            float* pw = &Ws[SW(r, c)];
            pw[0] = __uint_as_float(f2tf(wv.x));
            pw[1] = __uint_as_float(f2tf(wv.y));
            pw[2] = __uint_as_float(f2tf(wv.z));
            pw[3] = __uint_as_float(f2tf(wv.w));
        }
        __syncthreads();

        #pragma unroll
        for (int ks = 0; ks < 8; ks++) {
            unsigned af[2][4];
            #pragma unroll
            for (int g = 0; g < 2; g++) {
                int rb = warp * 32 + g * 16 + grp;
                af[g][0] = __float_as_uint(Xs[SW(rb,     ks*8 + qr)]);
                af[g][1] = __float_as_uint(Xs[SW(rb + 8, ks*8 + qr)]);
                af[g][2] = __float_as_uint(Xs[SW(rb,     ks*8 + qr + 4)]);
                af[g][3] = __float_as_uint(Xs[SW(rb + 8, ks*8 + qr + 4)]);
            }
            #pragma unroll
            for (int nt = 0; nt < 8; nt++) {
                unsigned b0 = __float_as_uint(Ws[SW(ks*8 + qr,     nt*8 + grp)]);
                unsigned b1 = __float_as_uint(Ws[SW(ks*8 + qr + 4, nt*8 + grp)]);
                mma_tf32(acc[0][nt], af[0], b0, b1);
                mma_tf32(acc[1][nt], af[1], b0, b1);
            }
        }
    }

    #pragma unroll
    for (int g = 0; g < 2; g++) {
        int rb = warp * 32 + g * 16 + grp;
        #pragma unroll
        for (int nt = 0; nt < 8; nt++) {
            int c = nt*8 + 2*qr;
            float2 bv2 = make_float2(bo[n0 + c], bo[n0 + c + 1]);
            *(float2*)&out[(size_t)(s0 + rb) * D + n0 + c] =
                make_float2(acc[g][nt][0] + bv2.x, acc[g][nt][1] + bv2.y);
            *(float2*)&out[(size_t)(s0 + rb + 8) * D + n0 + c] =
                make_float2(acc[g][nt][2] + bv2.x, acc[g][nt][3] + bv2.y);
        }
    }
}

// ---------------------------------------------------------------------------
extern "C" void kernel_launch(void* const* d_in, const int* in_sizes, int n_in,
                              void* d_out, int out_size)
{
    const float* query = (const float*)d_in[0];
    const float* key   = (const float*)d_in[1];
    const float* value = (const float*)d_in[2];
    const float* Wq    = (const float*)d_in[3];
    const float* bq    = (const float*)d_in[4];
    const float* Wk    = (const float*)d_in[5];
    const float* bk    = (const float*)d_in[6];
    const float* Wv    = (const float*)d_in[7];
    const float* bv    = (const float*)d_in[8];
    const float* Wo    = (const float*)d_in[9];
    const float* bo    = (const float*)d_in[10];
    float* out = (float*)d_out;

    (void)in_sizes; (void)n_in; (void)out_size;

    proj_tf32_kernel<<<dim3(S / 128, 3 * B * H), 128>>>(query, key, value,
                                                        Wq, Wk, Wv, bq, bk, bv);

    // 96KB dynamic smem: attribute set is idempotent and capture-safe
    // (no stream work, no allocation).
    static const int ATTN_SMEM = 24576 * (int)sizeof(float);   // 98304 B
    cudaFuncSetAttribute(attn_mma_kernel,
                         cudaFuncAttributeMaxDynamicSharedMemorySize, ATTN_SMEM);
    attn_mma_kernel<<<dim3(S / 128, B * H), 128, ATTN_SMEM>>>();

    out_proj_tf32_kernel<<<dim3(D / 64, (B * S) / 128), 128>>>(Wo, bo, out);
}

// round 6
// speedup vs baseline: 4.3571x; 1.0997x over previous
#include <cuda_runtime.h>
#include <math.h>

#define B 4
#define S 2048
#define D 512
#define H 8
#define A 64
#define HA (H*A)

// Scratch (allocation-free rule: __device__ globals)
__device__ float g_q[(size_t)B*H*S*A];     // proj outputs, tf32-rounded
__device__ float g_k[(size_t)B*H*S*A];
__device__ float g_v[(size_t)B*H*S*A];
__device__ float g_attn[(size_t)B*S*HA];   // attention out, tf32-rounded
// tf32-rounded copies of inputs/weights (pre-pass)
__device__ float g_xq[(size_t)B*S*D];
__device__ float g_xk[(size_t)B*S*D];
__device__ float g_xv[(size_t)B*S*D];
__device__ float g_wq[(size_t)H*D*A];
__device__ float g_wk[(size_t)H*D*A];
__device__ float g_wv[(size_t)H*D*A];
__device__ float g_wo[(size_t)HA*D];

// ---------------------------------------------------------------------------
// helpers
// ---------------------------------------------------------------------------
__device__ __forceinline__ unsigned f2tf(float x) {
    unsigned u;
    asm("cvt.rna.tf32.f32 %0, %1;" : "=r"(u) : "f"(x));
    return u;
}

__device__ __forceinline__ void mma_tf32(float c[4], const unsigned a[4],
                                         unsigned b0, unsigned b1) {
    asm volatile("mma.sync.aligned.m16n8k8.row.col.f32.tf32.tf32.f32 "
                 "{%0,%1,%2,%3}, {%4,%5,%6,%7}, {%8,%9}, {%0,%1,%2,%3};"
                 : "+f"(c[0]), "+f"(c[1]), "+f"(c[2]), "+f"(c[3])
                 : "r"(a[0]), "r"(a[1]), "r"(a[2]), "r"(a[3]),
                   "r"(b0), "r"(b1));
}

__device__ __forceinline__ void cpa16(float* dst_smem, const float* src) {
    unsigned d = (unsigned)__cvta_generic_to_shared(dst_smem);
    asm volatile("cp.async.cg.shared.global [%0], [%1], 16;" :: "r"(d), "l"(src));
}
#define CPA_COMMIT() asm volatile("cp.async.commit_group;")
#define CPA_WAIT(n)  asm volatile("cp.async.wait_group %0;" :: "n"(n))

// XOR swizzle: flip bits [3:5] of the column by row&7. 16B groups (c%4==0)
// stay contiguous (only bits >=3 flip), so cp.async 16B works on SW addresses.
#define SW(r, c) ((r)*64 + ((c) ^ (((r)&7) << 3)))
#define FU(x) __float_as_uint(x)

// ---------------------------------------------------------------------------
// Kernel 0: tf32 pre-rounding pass (elementwise, float4).
// which: 0..2 -> g_xq/g_xk/g_xv, 3..5 -> g_wq/g_wk/g_wv, 6 -> g_wo
// ---------------------------------------------------------------------------
__global__ void round_tf32_kernel(const float* __restrict__ src, int which, int n4)
{
    float* dst = (which == 0) ? g_xq : (which == 1) ? g_xk : (which == 2) ? g_xv
               : (which == 3) ? g_wq : (which == 4) ? g_wk : (which == 5) ? g_wv
               : g_wo;
    int i = blockIdx.x * blockDim.x + threadIdx.x;
    if (i < n4) {
        float4 v = ((const float4*)src)[i];
        v.x = __uint_as_float(f2tf(v.x));
        v.y = __uint_as_float(f2tf(v.y));
        v.z = __uint_as_float(f2tf(v.z));
        v.w = __uint_as_float(f2tf(v.w));
        ((float4*)dst)[i] = v;
    }
}

// ---------------------------------------------------------------------------
// Kernel 1: fused QKV projection, tf32, cp.async double-buffered.
// CTA = 128(M) x 64(N=A), 4 warps x 32 rows. Inputs pre-rounded -> staging is
// pure cp.async. Dynamic smem 96KB: X[2]x(128x64) + W[2]x(64x64).
// Epilogue stores tf32-rounded (consumed by attention staging).
// grid: (S/128, 3*B*H), 128 threads.
// ---------------------------------------------------------------------------
__global__ void __launch_bounds__(128) proj_tf32_kernel(
    const float* __restrict__ bq, const float* __restrict__ bk,
    const float* __restrict__ bv)
{
    extern __shared__ float sm[];
    float* Xb[2] = { sm,          sm + 8192  };
    float* Wb[2] = { sm + 16384,  sm + 20480 };

    const int z  = blockIdx.y;
    const int p  = z / (B*H);
    const int bh = z % (B*H);
    const int b  = bh / H;
    const int h  = bh % H;

    const float* x    = (p == 0 ? g_xq : p == 1 ? g_xk : g_xv) + (size_t)b * S * D;
    const float* W    = (p == 0 ? g_wq : p == 1 ? g_wk : g_wv) + (size_t)h * D * A;
    const float* bias = (p == 0 ? bq   : p == 1 ? bk   : bv)   + h * A;
    float* out        = (p == 0 ? g_q  : p == 1 ? g_k  : g_v)  + (size_t)bh * S * A;

    const int s0   = blockIdx.x * 128;
    const int tid  = threadIdx.x;
    const int warp = tid >> 5;
    const int lane = tid & 31;
    const int grp  = lane >> 2;
    const int qr   = lane & 3;

    float acc[2][8][4];
    #pragma unroll
    for (int g = 0; g < 2; g++)
        #pragma unroll
        for (int nt = 0; nt < 8; nt++)
            #pragma unroll
            for (int j = 0; j < 4; j++) acc[g][nt][j] = 0.0f;

    // ---- stage chunk 0 ----
    {
        #pragma unroll
        for (int u = 0; u < 16; u++) {
            int idx = (u * 128 + tid) * 4;
            int r = idx >> 6, c = idx & 63;
            cpa16(&Xb[0][SW(r, c)], &x[(size_t)(s0 + r) * D + c]);
        }
        #pragma unroll
        for (int u = 0; u < 8; u++) {
            int idx = (u * 128 + tid) * 4;
            int r = idx >> 6, c = idx & 63;
            cpa16(&Wb[0][SW(r, c)], &W[(size_t)r * A + c]);
        }
        CPA_COMMIT();
    }

    for (int ci = 0; ci < 8; ci++) {
        if (ci < 7) {
            int k0 = (ci + 1) * 64;
            float* Xd = Xb[(ci + 1) & 1];
            float* Wd = Wb[(ci + 1) & 1];
            #pragma unroll
            for (int u = 0; u < 16; u++) {
                int idx = (u * 128 + tid) * 4;
                int r = idx >> 6, c = idx & 63;
                cpa16(&Xd[SW(r, c)], &x[(size_t)(s0 + r) * D + k0 + c]);
            }
            #pragma unroll
            for (int u = 0; u < 8; u++) {
                int idx = (u * 128 + tid) * 4;
                int r = idx >> 6, c = idx & 63;
                cpa16(&Wd[SW(r, c)], &W[(size_t)(k0 + r) * A + c]);
            }
            CPA_COMMIT();
            CPA_WAIT(1);
        } else {
            CPA_WAIT(0);
        }
        __syncthreads();

        const float* Xd = Xb[ci & 1];
        const float* Wd = Wb[ci & 1];
        #pragma unroll
        for (int ks = 0; ks < 8; ks++) {
            unsigned af[2][4];
            #pragma unroll
            for (int g = 0; g < 2; g++) {
                int rb = warp * 32 + g * 16 + grp;
                af[g][0] = FU(Xd[SW(rb,     ks*8 + qr)]);
                af[g][1] = FU(Xd[SW(rb + 8, ks*8 + qr)]);
                af[g][2] = FU(Xd[SW(rb,     ks*8 + qr + 4)]);
                af[g][3] = FU(Xd[SW(rb + 8, ks*8 + qr + 4)]);
            }
            #pragma unroll
            for (int nt = 0; nt < 8; nt++) {
                unsigned b0 = FU(Wd[SW(ks*8 + qr,     nt*8 + grp)]);
                unsigned b1 = FU(Wd[SW(ks*8 + qr + 4, nt*8 + grp)]);
                mma_tf32(acc[0][nt], af[0], b0, b1);
                mma_tf32(acc[1][nt], af[1], b0, b1);
            }
        }
        __syncthreads();   // frees buf ci&1 for stage ci+2
    }

    #pragma unroll
    for (int g = 0; g < 2; g++) {
        int rb = warp * 32 + g * 16 + grp;
        #pragma unroll
        for (int nt = 0; nt < 8; nt++) {
            int c = nt*8 + 2*qr;
            float2 bv2 = make_float2(bias[c], bias[c+1]);
            *(float2*)&out[(size_t)(s0 + rb) * A + c] = make_float2(
                __uint_as_float(f2tf(acc[g][nt][0] + bv2.x)),
                __uint_as_float(f2tf(acc[g][nt][1] + bv2.y)));
            *(float2*)&out[(size_t)(s0 + rb + 8) * A + c] = make_float2(
                __uint_as_float(f2tf(acc[g][nt][2] + bv2.x)),
                __uint_as_float(f2tf(acc[g][nt][3] + bv2.y)));
        }
    }
}

// ---------------------------------------------------------------------------
// Kernel 2: flash attention, tf32, 128 query rows per CTA (32 rows/warp).
// K/V pre-rounded by proj epilogue -> staging is pure cp.async. Q scale by
// 1/8 is exact (power of two), so no re-rounding needed.
// Dynamic smem (96KB): Qs 128x64 | Ks 64x64 | Vs 64x64 | Ps 128x64.
// Causal block-skip (j<=i masked); last CTA (row S-1 fully masked -> uniform
// over ALL S keys) keeps the full loop. grid: (S/128, B*H), 128 threads.
// ---------------------------------------------------------------------------
__global__ void __launch_bounds__(128) attn_mma_kernel()
{
    extern __shared__ float sm[];
    float* Qs = sm;              // 128*64
    float* Ks = sm + 8192;       // 64*64
    float* Vs = sm + 12288;      // 64*64
    float* Ps = sm + 16384;      // 128*64

    const int bh = blockIdx.y;
    const int b  = bh / H;
    const int h  = bh % H;
    const int qb = blockIdx.x * 128;
    const int tid  = threadIdx.x;
    const int warp = tid >> 5;
    const int lane = tid & 31;
    const int grp  = lane >> 2;
    const int qr   = lane & 3;

    // ---- stage Q (scaled by 1/sqrt(A), exact for tf32 values) ----
    const float* qg = g_q + ((size_t)bh * S + qb) * 64;
    #pragma unroll
    for (int u = 0; u < 16; u++) {
        int idx = (u * 128 + tid) * 4;
        int r = idx >> 6, c = idx & 63;
        float4 v = *(const float4*)&qg[idx];
        float* p = &Qs[SW(r, c)];
        p[0] = v.x * 0.125f; p[1] = v.y * 0.125f;
        p[2] = v.z * 0.125f; p[3] = v.w * 0.125f;
    }

    float oacc[2][8][4];
    #pragma unroll
    for (int g = 0; g < 2; g++)
        #pragma unroll
        for (int nt = 0; nt < 8; nt++)
            #pragma unroll
            for (int j = 0; j < 4; j++) oacc[g][nt][j] = 0.0f;

    float m[4], l[4];
    #pragma unroll
    for (int q = 0; q < 4; q++) { m[q] = -INFINITY; l[q] = 0.0f; }

    const float* kg = g_k + (size_t)bh * S * 64;
    const float* vg = g_v + (size_t)bh * S * 64;

    const int j_start = (qb == S - 128) ? 0 : qb;

    for (int j0 = j_start; j0 < S; j0 += 64) {
        __syncthreads();
        // ---- stage K, V block via cp.async (pure copy) ----
        #pragma unroll
        for (int u = 0; u < 8; u++) {
            int idx = (u * 128 + tid) * 4;
            int r = idx >> 6, c = idx & 63;
            cpa16(&Ks[SW(r, c)], &kg[(size_t)j0 * 64 + idx]);
            cpa16(&Vs[SW(r, c)], &vg[(size_t)j0 * 64 + idx]);
        }
        CPA_COMMIT();
        CPA_WAIT(0);
        __syncthreads();

        // ---- S = Q * K^T ----
        float sacc[2][8][4];
        #pragma unroll
        for (int g = 0; g < 2; g++)
            #pragma unroll
            for (int nt = 0; nt < 8; nt++)
                #pragma unroll
                for (int j = 0; j < 4; j++) sacc[g][nt][j] = 0.0f;

        #pragma unroll
        for (int ks = 0; ks < 8; ks++) {
            unsigned qa[2][4];
            #pragma unroll
            for (int g = 0; g < 2; g++) {
                int rb = warp * 32 + g * 16 + grp;
                qa[g][0] = FU(Qs[SW(rb,     ks*8 + qr)]);
                qa[g][1] = FU(Qs[SW(rb + 8, ks*8 + qr)]);
                qa[g][2] = FU(Qs[SW(rb,     ks*8 + qr + 4)]);
                qa[g][3] = FU(Qs[SW(rb + 8, ks*8 + qr + 4)]);
            }
            #pragma unroll
            for (int nt = 0; nt < 8; nt++) {
                unsigned b0 = FU(Ks[SW(nt*8 + grp, ks*8 + qr)]);
                unsigned b1 = FU(Ks[SW(nt*8 + grp, ks*8 + qr + 4)]);
                mma_tf32(sacc[0][nt], qa[0], b0, b1);
                mma_tf32(sacc[1][nt], qa[1], b0, b1);
            }
        }

        // ---- mask + online softmax per row group ----
        #pragma unroll
        for (int g = 0; g < 2; g++) {
            const int iA = qb + warp * 32 + g * 16 + grp;
            const int iB = iA + 8;
            float tmaxA = -INFINITY, tmaxB = -INFINITY;
            #pragma unroll
            for (int nt = 0; nt < 8; nt++) {
                int j = j0 + nt*8 + 2*qr;
                if (j     <= iA) sacc[g][nt][0] = -1.0e9f;
                if (j + 1 <= iA) sacc[g][nt][1] = -1.0e9f;
                if (j     <= iB) sacc[g][nt][2] = -1.0e9f;
                if (j + 1 <= iB) sacc[g][nt][3] = -1.0e9f;
                tmaxA = fmaxf(tmaxA, fmaxf(sacc[g][nt][0], sacc[g][nt][1]));
                tmaxB = fmaxf(tmaxB, fmaxf(sacc[g][nt][2], sacc[g][nt][3]));
            }
            tmaxA = fmaxf(tmaxA, __shfl_xor_sync(0xffffffffu, tmaxA, 1));
            tmaxA = fmaxf(tmaxA, __shfl_xor_sync(0xffffffffu, tmaxA, 2));
            tmaxB = fmaxf(tmaxB, __shfl_xor_sync(0xffffffffu, tmaxB, 1));
            tmaxB = fmaxf(tmaxB, __shfl_xor_sync(0xffffffffu, tmaxB, 2));

            float mnA = fmaxf(m[2*g],   tmaxA);
            float mnB = fmaxf(m[2*g+1], tmaxB);
            float crA = __expf(m[2*g]   - mnA);   // first block: exp(-inf)=0
            float crB = __expf(m[2*g+1] - mnB);
            l[2*g]   *= crA; l[2*g+1] *= crB;
            m[2*g]    = mnA; m[2*g+1]  = mnB;
            #pragma unroll
            for (int nt = 0; nt < 8; nt++) {
                oacc[g][nt][0] *= crA; oacc[g][nt][1] *= crA;
                oacc[g][nt][2] *= crB; oacc[g][nt][3] *= crB;
            }

            float lsA = 0.0f, lsB = 0.0f;
            int rb = warp * 32 + g * 16 + grp;
            #pragma unroll
            for (int nt = 0; nt < 8; nt++) {
                float p0 = __expf(sacc[g][nt][0] - mnA);
                float p1 = __expf(sacc[g][nt][1] - mnA);
                float p2 = __expf(sacc[g][nt][2] - mnB);
                float p3 = __expf(sacc[g][nt][3] - mnB);
                lsA += p0 + p1; lsB += p2 + p3;
                int c = nt*8 + 2*qr;
                *(float2*)&Ps[SW(rb, c)] =
                    make_float2(__uint_as_float(f2tf(p0)), __uint_as_float(f2tf(p1)));
                *(float2*)&Ps[SW(rb + 8, c)] =
                    make_float2(__uint_as_float(f2tf(p2)), __uint_as_float(f2tf(p3)));
            }
            l[2*g] += lsA; l[2*g+1] += lsB;
        }
        __syncwarp();   // P rows are warp-private; order stores before loads

        // ---- O += P * V ----
        #pragma unroll
        for (int ks = 0; ks < 8; ks++) {
            unsigned pa[2][4];
            #pragma unroll
            for (int g = 0; g < 2; g++) {
                int rb = warp * 32 + g * 16 + grp;
                pa[g][0] = FU(Ps[SW(rb,     ks*8 + qr)]);
                pa[g][1] = FU(Ps[SW(rb + 8, ks*8 + qr)]);
                pa[g][2] = FU(Ps[SW(rb,     ks*8 + qr + 4)]);
                pa[g][3] = FU(Ps[SW(rb + 8, ks*8 + qr + 4)]);
            }
            #pragma unroll
            for (int nt = 0; nt < 8; nt++) {
                unsigned b0 = FU(Vs[SW(ks*8 + qr,     nt*8 + grp)]);
                unsigned b1 = FU(Vs[SW(ks*8 + qr + 4, nt*8 + grp)]);
                mma_tf32(oacc[0][nt], pa[0], b0, b1);
                mma_tf32(oacc[1][nt], pa[1], b0, b1);
            }
        }
    }

    // ---- quad-reduce softmax denominators ----
    #pragma unroll
    for (int q = 0; q < 4; q++) {
        l[q] += __shfl_xor_sync(0xffffffffu, l[q], 1);
        l[q] += __shfl_xor_sync(0xffffffffu, l[q], 2);
    }

    // ---- epilogue: normalize, round to tf32, write head-concat layout ----
    #pragma unroll
    for (int g = 0; g < 2; g++) {
        const int iA = qb + warp * 32 + g * 16 + grp;
        const float invA = 1.0f / l[2*g];
        const float invB = 1.0f / l[2*g+1];
        float* obA = g_attn + ((size_t)b * S + iA) * HA + h * A;
        float* obB = g_attn + ((size_t)b * S + iA + 8) * HA + h * A;
        #pragma unroll
        for (int nt = 0; nt < 8; nt++) {
            int c = nt*8 + 2*qr;
            *(float2*)&obA[c] = make_float2(
                __uint_as_float(f2tf(oacc[g][nt][0] * invA)),
                __uint_as_float(f2tf(oacc[g][nt][1] * invA)));
            *(float2*)&obB[c] = make_float2(
                __uint_as_float(f2tf(oacc[g][nt][2] * invB)),
                __uint_as_float(f2tf(oacc[g][nt][3] * invB)));
        }
    }
}

// ---------------------------------------------------------------------------
// Kernel 3: output projection, tf32, cp.async double-buffered.
// out[M=B*S, N=D] = g_attn[M, HA] @ Wo[HA, D] + bo
// CTA 128x64, same pipeline as proj. Final output NOT rounded.
// grid: (D/64, B*S/128), 128 threads.
// ---------------------------------------------------------------------------
__global__ void __launch_bounds__(128) out_proj_tf32_kernel(
    const float* __restrict__ bo, float* __restrict__ out)
{
    extern __shared__ float sm[];
    float* Xb[2] = { sm,          sm + 8192  };
    float* Wb[2] = { sm + 16384,  sm + 20480 };

    const int n0 = blockIdx.x * 64;
    const int s0 = blockIdx.y * 128;
    const int tid  = threadIdx.x;
    const int warp = tid >> 5;
    const int lane = tid & 31;
    const int grp  = lane >> 2;
    const int qr   = lane & 3;

    float acc[2][8][4];
    #pragma unroll
    for (int g = 0; g < 2; g++)
        #pragma unroll
        for (int nt = 0; nt < 8; nt++)
            #pragma unroll
            for (int j = 0; j < 4; j++) acc[g][nt][j] = 0.0f;

    {
        #pragma unroll
        for (int u = 0; u < 16; u++) {
            int idx = (u * 128 + tid) * 4;
            int r = idx >> 6, c = idx & 63;
            cpa16(&Xb[0][SW(r, c)], &g_attn[(size_t)(s0 + r) * HA + c]);
        }
        #pragma unroll
        for (int u = 0; u < 8; u++) {
            int idx = (u * 128 + tid) * 4;
            int r = idx >> 6, c = idx & 63;
            cpa16(&Wb[0][SW(r, c)], &g_wo[(size_t)r * D + n0 + c]);
        }
        CPA_COMMIT();
    }

    for (int ci = 0; ci < 8; ci++) {
        if (ci < 7) {
            int k0 = (ci + 1) * 64;
            float* Xd = Xb[(ci + 1) & 1];
            float* Wd = Wb[(ci + 1) & 1];
            #pragma unroll
            for (int u = 0; u < 16; u++) {
                int idx = (u * 128 + tid) * 4;
                int r = idx >> 6, c = idx & 63;
                cpa16(&Xd[SW(r, c)], &g_attn[(size_t)(s0 + r) * HA + k0 + c]);
            }
            #pragma unroll
            for (int u = 0; u < 8; u++) {
                int idx = (u * 128 + tid) * 4;
                int r = idx >> 6, c = idx & 63;
                cpa16(&Wd[SW(r, c)], &g_wo[(size_t)(k0 + r) * D + n0 + c]);
            }
            CPA_COMMIT();
            CPA_WAIT(1);
        } else {
            CPA_WAIT(0);
        }
        __syncthreads();

        const float* Xd = Xb[ci & 1];
        const float* Wd = Wb[ci & 1];
        #pragma unroll
        for (int ks = 0; ks < 8; ks++) {
            unsigned af[2][4];
            #pragma unroll
            for (int g = 0; g < 2; g++) {
                int rb = warp * 32 + g * 16 + grp;
                af[g][0] = FU(Xd[SW(rb,     ks*8 + qr)]);
                af[g][1] = FU(Xd[SW(rb + 8, ks*8 + qr)]);
                af[g][2] = FU(Xd[SW(rb,     ks*8 + qr + 4)]);
                af[g][3] = FU(Xd[SW(rb + 8, ks*8 + qr + 4)]);
            }
            #pragma unroll
            for (int nt = 0; nt < 8; nt++) {
                unsigned b0 = FU(Wd[SW(ks*8 + qr,     nt*8 + grp)]);
                unsigned b1 = FU(Wd[SW(ks*8 + qr + 4, nt*8 + grp)]);
                mma_tf32(acc[0][nt], af[0], b0, b1);
                mma_tf32(acc[1][nt], af[1], b0, b1);
            }
        }
        __syncthreads();
    }

    #pragma unroll
    for (int g = 0; g < 2; g++) {
        int rb = warp * 32 + g * 16 + grp;
        #pragma unroll
        for (int nt = 0; nt < 8; nt++) {
            int c = nt*8 + 2*qr;
            float2 bv2 = make_float2(bo[n0 + c], bo[n0 + c + 1]);
            *(float2*)&out[(size_t)(s0 + rb) * D + n0 + c] =
                make_float2(acc[g][nt][0] + bv2.x, acc[g][nt][1] + bv2.y);
            *(float2*)&out[(size_t)(s0 + rb + 8) * D + n0 + c] =
                make_float2(acc[g][nt][2] + bv2.x, acc[g][nt][3] + bv2.y);
        }
    }
}

// ---------------------------------------------------------------------------
extern "C" void kernel_launch(void* const* d_in, const int* in_sizes, int n_in,
                              void* d_out, int out_size)
{
    const float* query = (const float*)d_in[0];
    const float* key   = (const float*)d_in[1];
    const float* value = (const float*)d_in[2];
    const float* Wq    = (const float*)d_in[3];
    const float* bq    = (const float*)d_in[4];
    const float* Wk    = (const float*)d_in[5];
    const float* bk    = (const float*)d_in[6];
    const float* Wv    = (const float*)d_in[7];
    const float* bv    = (const float*)d_in[8];
    const float* Wo    = (const float*)d_in[9];
    const float* bo    = (const float*)d_in[10];
    float* out = (float*)d_out;

    (void)in_sizes; (void)n_in; (void)out_size;

    // ---- pre-round inputs & weights to tf32 (rna), once ----
    const int nx4 = (B * S * D) / 4;       // 1048576
    const int nw4 = (H * D * A) / 4;       // 65536
    const int no4 = (HA * D) / 4;          // 65536
    round_tf32_kernel<<<(nx4 + 255) / 256, 256>>>(query, 0, nx4);
    round_tf32_kernel<<<(nx4 + 255) / 256, 256>>>(key,   1, nx4);
    round_tf32_kernel<<<(nx4 + 255) / 256, 256>>>(value, 2, nx4);
    round_tf32_kernel<<<(nw4 + 255) / 256, 256>>>(Wq,    3, nw4);
    round_tf32_kernel<<<(nw4 + 255) / 256, 256>>>(Wk,    4, nw4);
    round_tf32_kernel<<<(nw4 + 255) / 256, 256>>>(Wv,    5, nw4);
    round_tf32_kernel<<<(no4 + 255) / 256, 256>>>(Wo,    6, no4);

    // dynamic smem attribute sets: idempotent, capture-safe, no allocation
    static const int SMEM96 = 24576 * (int)sizeof(float);   // 98304 B
    cudaFuncSetAttribute(proj_tf32_kernel,
                         cudaFuncAttributeMaxDynamicSharedMemorySize, SMEM96);
    cudaFuncSetAttribute(attn_mma_kernel,
                         cudaFuncAttributeMaxDynamicSharedMemorySize, SMEM96);
    cudaFuncSetAttribute(out_proj_tf32_kernel,
                         cudaFuncAttributeMaxDynamicSharedMemorySize, SMEM96);

    proj_tf32_kernel<<<dim3(S / 128, 3 * B * H), 128, SMEM96>>>(bq, bk, bv);

    attn_mma_kernel<<<dim3(S / 128, B * H), 128, SMEM96>>>();

    out_proj_tf32_kernel<<<dim3(D / 64, (B * S) / 128), 128, SMEM96>>>(bo, out);
}